// round 15
// baseline (speedup 1.0000x reference)
#include <cuda_runtime.h>

#define NROWS 262144
#define DDIM  256
#define NCLUS 512
#define NPAIRS (NCLUS * (NCLUS - 1) / 2)   // 130816

#define COLG   16                 // column groups (16 floats = 64B each)
#define CHUNKS 16                 // row chunks
#define SCTAS  (COLG * CHUNKS)    // 256 stream CTAs
#define RPC    (NROWS / CHUNKS)   // 16384 rows per chunk
#define W      16                 // floats per col-group
#define WP     17                 // padded stride (bank-conflict-free)

// ---------------- scratch (static __device__, zero-initialized) -------------
__device__ float g_part[SCTAS * NCLUS * W];   // 8MB partial sums (overwritten)
__device__ int   g_cnt[NCLUS];                // label counts; reset in k_pdist
__device__ float g_cent[NCLUS * DDIM];        // normalized centers
__device__ float g_accum;                     // zeroed in k_stream
__device__ int   g_done;                      // self-resetting

// ---------------- kernel 1: streaming column-sliced scatter-accumulate ------
__global__ __launch_bounds__(256) void k_stream(const float* __restrict__ M,
                                                const int* __restrict__ label) {
    __shared__ float s_acc[NCLUS * WP];   // 512 x 17 floats = 34816 B
    __shared__ int   s_lcnt[NCLUS];
    const int t    = threadIdx.x;
    const int bid  = blockIdx.x;
    const int g    = bid & (COLG - 1);    // col group
    const int k    = bid >> 4;            // row chunk
    const int rbase = k * RPC;
    const int rowoff = t >> 2;            // 0..63
    const int colq   = t & 3;             // float4 within group

    // zero accumulators (+ counts for g==0)
    for (int i = t; i < NCLUS * WP; i += 256) s_acc[i] = 0.0f;
    if (g == 0) { s_lcnt[t] = 0; s_lcnt[t + 256] = 0; }
    if (bid == 0 && t == 0) g_accum = 0.0f;
    __syncthreads();

    const float4* __restrict__ Mv = (const float4*)M;
    const int cbase = g * 4 + colq;       // float4 column index

    // 256 tiles of 64 rows, unrolled 4 for MLP
    for (int it = 0; it < RPC / 64; it += 4) {
        int    lb[4];
        float4 vv[4];
#pragma unroll
        for (int j = 0; j < 4; j++) {
            int r = rbase + (it + j) * 64 + rowoff;
            lb[j] = __ldg(&label[r]);
            vv[j] = __ldg(&Mv[(size_t)r * 64 + cbase]);
        }
#pragma unroll
        for (int j = 0; j < 4; j++) {
            float* sa = s_acc + lb[j] * WP + colq * 4;
            atomicAdd(sa + 0, vv[j].x);
            atomicAdd(sa + 1, vv[j].y);
            atomicAdd(sa + 2, vv[j].z);
            atomicAdd(sa + 3, vv[j].w);
        }
        if (g == 0 && colq == 0) {
#pragma unroll
            for (int j = 0; j < 4; j++) atomicAdd(&s_lcnt[lb[j]], 1);
        }
    }
    __syncthreads();

    // write partials (strip padding), coalesced
    float* dst = g_part + (size_t)bid * (NCLUS * W);
    for (int idx = t; idx < NCLUS * W; idx += 256) {
        int l = idx >> 4, cc = idx & 15;
        dst[idx] = s_acc[l * WP + cc];
    }
    // counts (only chunk histograms from g==0 CTAs)
    if (g == 0) {
        for (int c = t; c < NCLUS; c += 256) {
            int n = s_lcnt[c];
            if (n > 0) atomicAdd(&g_cnt[c], n);
        }
    }
}

// ---------------- kernel 2: fold 16 chunk-partials + normalize --------------
__global__ __launch_bounds__(256) void k_reduce() {
    const int c   = blockIdx.x;          // cluster
    const int col = threadIdx.x;         // 0..255
    const int gg  = col >> 4, cc = col & 15;
    float s = 0.0f;
#pragma unroll
    for (int k = 0; k < CHUNKS; k++)
        s += g_part[(size_t)((k << 4) + gg) * (NCLUS * W) + c * W + cc];
    int n = g_cnt[c];
    g_cent[c * DDIM + col] = s / (float)(n > 0 ? n : 1);
}

// ---------------- kernel 3: tiled pdist + finalize --------------------------
#define PT 32
#define DCH 64
#define NT (NCLUS / PT)                 // 16 -> 136 blocks
#define PDIST_BLOCKS (NT * (NT + 1) / 2)
__global__ __launch_bounds__(256) void k_pdist(float* __restrict__ out) {
    __shared__ float Ci[PT][DCH + 1];
    __shared__ float Cj[PT][DCH + 1];
    __shared__ float red[8];

    // reset label counters for next graph replay (k_reduce already consumed them)
    if (blockIdx.x < 128 && threadIdx.x < 4)
        g_cnt[blockIdx.x * 4 + threadIdx.x] = 0;

    int b = blockIdx.x;
    int bi = 0, nb = NT;
    while (b >= nb) { b -= nb; bi++; nb--; }
    int bj = bi + b;
    const int i0 = bi * PT, j0 = bj * PT;

    const int tid = threadIdx.x;
    const int tx = tid & 15, ty = tid >> 4;

    float s00 = 0.f, s01 = 0.f, s10 = 0.f, s11 = 0.f;

    for (int dbase = 0; dbase < DDIM; dbase += DCH) {
        for (int idx = tid; idx < PT * DCH; idx += 256) {
            int r = idx / DCH, col = idx % DCH;
            Ci[r][col] = g_cent[(i0 + r) * DDIM + dbase + col];
            Cj[r][col] = g_cent[(j0 + r) * DDIM + dbase + col];
        }
        __syncthreads();
#pragma unroll 8
        for (int d = 0; d < DCH; d++) {
            float ia = Ci[2 * ty + 0][d];
            float ib = Ci[2 * ty + 1][d];
            float ja = Cj[2 * tx + 0][d];
            float jb = Cj[2 * tx + 1][d];
            float d00 = ia - ja; s00 += d00 * d00;
            float d01 = ia - jb; s01 += d01 * d01;
            float d10 = ib - ja; s10 += d10 * d10;
            float d11 = ib - jb; s11 += d11 * d11;
        }
        __syncthreads();
    }

    float local = 0.f;
    {
        int gi0 = i0 + 2 * ty, gi1 = gi0 + 1;
        int gj0 = j0 + 2 * tx, gj1 = gj0 + 1;
        if (gj0 > gi0) local += sqrtf(fmaxf(s00, 1e-12f));
        if (gj1 > gi0) local += sqrtf(fmaxf(s01, 1e-12f));
        if (gj0 > gi1) local += sqrtf(fmaxf(s10, 1e-12f));
        if (gj1 > gi1) local += sqrtf(fmaxf(s11, 1e-12f));
    }
#pragma unroll
    for (int off = 16; off > 0; off >>= 1)
        local += __shfl_down_sync(0xffffffffu, local, off);
    if ((tid & 31) == 0) red[tid >> 5] = local;
    __syncthreads();
    if (tid == 0) {
        float blk = 0.f;
#pragma unroll
        for (int w = 0; w < 8; w++) blk += red[w];
        atomicAdd(&g_accum, blk);
        __threadfence();
        int prev = atomicAdd(&g_done, 1);
        if (prev == PDIST_BLOCKS - 1) {
            g_done = 0;
            out[0] = -g_accum / (float)NPAIRS;
        }
    }
}

extern "C" void kernel_launch(void* const* d_in, const int* in_sizes, int n_in,
                              void* d_out, int out_size) {
    const float* matrix = (const float*)d_in[0];
    const int*   label  = (const int*)d_in[1];
    float* out = (float*)d_out;

    k_stream<<<SCTAS, 256>>>(matrix, label);
    k_reduce<<<NCLUS, 256>>>();
    k_pdist<<<PDIST_BLOCKS, 256>>>(out);
}

// round 16
// speedup vs baseline: 1.9850x; 1.9850x over previous
#include <cuda_runtime.h>

#define NROWS 262144
#define DDIM  256
#define NCLUS 512
#define NPAIRS (NCLUS * (NCLUS - 1) / 2)   // 130816

#define SLACK 1024               // fixed region size per cluster (mean 512 + 22 sigma)
#define CSTRIDE 32               // pad claim counters to 128B (distinct L2 slices)
#define SORT_CTAS 1024
#define SORT_THREADS 256         // 1 row per thread
#define SEGS 4
#define CENTER_CTAS (NCLUS * SEGS)         // 2048

// ---------------- scratch (static __device__, zero-initialized) -------------
__device__ int      g_claim[NCLUS * CSTRIDE];   // padded claim counters; reset in k_pdist
__device__ float    g_inv[NCLUS];               // derived in k_center
__device__ int      g_perm[NCLUS * SLACK];      // fixed 1024-slot region per cluster (2MB)
__device__ float    g_sum[NCLUS * DDIM];        // zeroed in k_sort
__device__ float    g_accum;                    // zeroed in k_sort
__device__ int      g_done;                     // self-resetting

// ---------------- kernel 1: warp-level match_any claim + scatter ------------
// No smem, no barriers: each warp groups same-label lanes, leader claims a
// contiguous base in the cluster's fixed region, lanes write their slots.
__global__ __launch_bounds__(SORT_THREADS) void k_sort(const int* __restrict__ label) {
    const int t   = threadIdx.x;
    const int bid = blockIdx.x;
    const int i   = bid * SORT_THREADS + t;
    const int lane = t & 31;

    // zero this CTA's 128-float slice of g_sum (131072 / 1024 CTAs)
    if (t < 128) g_sum[bid * 128 + t] = 0.0f;
    if (bid == 0 && t == 0) g_accum = 0.0f;

    const int l = __ldg(&label[i]);

    unsigned grp  = __match_any_sync(0xffffffffu, l);
    int      rank = __popc(grp & ((1u << lane) - 1u));
    int      ldr  = __ffs(grp) - 1;
    int      base = 0;
    if (lane == ldr) base = atomicAdd(&g_claim[l * CSTRIDE], __popc(grp));
    base = __shfl_sync(0xffffffffu, base, ldr);

    int slot = base + rank;
    if (slot < SLACK) g_perm[(l << 10) + slot] = i;   // guard: never OOB
}

// ---------------- kernel 2: segmented gather-sum (HBM hot path) -------------
__global__ __launch_bounds__(256) void k_center(const float* __restrict__ M) {
    __shared__ int    sperm[1024];
    __shared__ float4 sred[3][64];
    const int c     = blockIdx.x >> 2;
    const int seg   = blockIdx.x & 3;
    const int t     = threadIdx.x;

    // derive per-cluster inverse count (g_claim final at kernel boundary)
    if (t == 0 && blockIdx.x < NCLUS) {
        int cc = g_claim[blockIdx.x * CSTRIDE];
        if (cc > SLACK) cc = SLACK;
        g_inv[blockIdx.x] = 1.0f / (float)(cc > 0 ? cc : 1);
    }

    int cnt = g_claim[c * CSTRIDE];
    if (cnt > SLACK) cnt = SLACK;
    const int start = c << 10;     // fixed region base
    const int s0    = (cnt * seg) >> 2;
    const int s1    = (cnt * (seg + 1)) >> 2;
    const int n     = s1 - s0;
    const int grp   = t >> 6;      // 0..3: row phase
    const int col4  = t & 63;      // float4 column

    const float4* __restrict__ Mv = (const float4*)M;
    float4 a0 = {0,0,0,0}, a1 = {0,0,0,0}, a2 = {0,0,0,0}, a3 = {0,0,0,0};

    {
        for (int r = t; r < n; r += 256) sperm[r] = g_perm[start + s0 + r];
        __syncthreads();
        int r = grp;
        for (; r + 12 < n; r += 16) {
            float4 v0 = __ldcs(&Mv[(size_t)sperm[r]      * 64 + col4]);
            float4 v1 = __ldcs(&Mv[(size_t)sperm[r + 4]  * 64 + col4]);
            float4 v2 = __ldcs(&Mv[(size_t)sperm[r + 8]  * 64 + col4]);
            float4 v3 = __ldcs(&Mv[(size_t)sperm[r + 12] * 64 + col4]);
            a0.x += v0.x; a0.y += v0.y; a0.z += v0.z; a0.w += v0.w;
            a1.x += v1.x; a1.y += v1.y; a1.z += v1.z; a1.w += v1.w;
            a2.x += v2.x; a2.y += v2.y; a2.z += v2.z; a2.w += v2.w;
            a3.x += v3.x; a3.y += v3.y; a3.z += v3.z; a3.w += v3.w;
        }
        for (; r < n; r += 4) {
            float4 v = __ldcs(&Mv[(size_t)sperm[r] * 64 + col4]);
            a0.x += v.x; a0.y += v.y; a0.z += v.z; a0.w += v.w;
        }
    }

    float4 acc;
    acc.x = (a0.x + a1.x) + (a2.x + a3.x);
    acc.y = (a0.y + a1.y) + (a2.y + a3.y);
    acc.z = (a0.z + a1.z) + (a2.z + a3.z);
    acc.w = (a0.w + a1.w) + (a2.w + a3.w);

    if (grp > 0) sred[grp - 1][col4] = acc;
    __syncthreads();
    if (grp == 0) {
        float4 b0 = sred[0][col4], b1 = sred[1][col4], b2 = sred[2][col4];
        acc.x += b0.x + b1.x + b2.x;
        acc.y += b0.y + b1.y + b2.y;
        acc.z += b0.z + b1.z + b2.z;
        acc.w += b0.w + b1.w + b2.w;
        float* dst = g_sum + c * DDIM + col4 * 4;
        atomicAdd(dst + 0, acc.x);
        atomicAdd(dst + 1, acc.y);
        atomicAdd(dst + 2, acc.z);
        atomicAdd(dst + 3, acc.w);
    }
}

// ---------------- kernel 3: tiled pdist (divide fused into load) + finalize -
#define PT 32
#define DCH 64
#define NT (NCLUS / PT)                 // 16 -> 136 blocks
#define PDIST_BLOCKS (NT * (NT + 1) / 2)
__global__ __launch_bounds__(256) void k_pdist(float* __restrict__ out) {
    __shared__ float Ci[PT][DCH + 1];
    __shared__ float Cj[PT][DCH + 1];
    __shared__ float red[8];

    // reset claim counters for next graph replay (ordered by kernel boundary)
    if (blockIdx.x < 128 && threadIdx.x < 4)
        g_claim[(blockIdx.x * 4 + threadIdx.x) * CSTRIDE] = 0;

    int b = blockIdx.x;
    int bi = 0, nb = NT;
    while (b >= nb) { b -= nb; bi++; nb--; }
    int bj = bi + b;
    const int i0 = bi * PT, j0 = bj * PT;

    const int tid = threadIdx.x;
    const int tx = tid & 15, ty = tid >> 4;

    float s00 = 0.f, s01 = 0.f, s10 = 0.f, s11 = 0.f;

    for (int dbase = 0; dbase < DDIM; dbase += DCH) {
        for (int idx = tid; idx < PT * DCH; idx += 256) {
            int r = idx / DCH, col = idx % DCH;
            Ci[r][col] = g_sum[(i0 + r) * DDIM + dbase + col] * g_inv[i0 + r];
            Cj[r][col] = g_sum[(j0 + r) * DDIM + dbase + col] * g_inv[j0 + r];
        }
        __syncthreads();
#pragma unroll 8
        for (int d = 0; d < DCH; d++) {
            float ia = Ci[2 * ty + 0][d];
            float ib = Ci[2 * ty + 1][d];
            float ja = Cj[2 * tx + 0][d];
            float jb = Cj[2 * tx + 1][d];
            float d00 = ia - ja; s00 += d00 * d00;
            float d01 = ia - jb; s01 += d01 * d01;
            float d10 = ib - ja; s10 += d10 * d10;
            float d11 = ib - jb; s11 += d11 * d11;
        }
        __syncthreads();
    }

    float local = 0.f;
    {
        int gi0 = i0 + 2 * ty, gi1 = gi0 + 1;
        int gj0 = j0 + 2 * tx, gj1 = gj0 + 1;
        if (gj0 > gi0) local += sqrtf(fmaxf(s00, 1e-12f));
        if (gj1 > gi0) local += sqrtf(fmaxf(s01, 1e-12f));
        if (gj0 > gi1) local += sqrtf(fmaxf(s10, 1e-12f));
        if (gj1 > gi1) local += sqrtf(fmaxf(s11, 1e-12f));
    }
#pragma unroll
    for (int off = 16; off > 0; off >>= 1)
        local += __shfl_down_sync(0xffffffffu, local, off);
    if ((tid & 31) == 0) red[tid >> 5] = local;
    __syncthreads();
    if (tid == 0) {
        float blk = 0.f;
#pragma unroll
        for (int w = 0; w < 8; w++) blk += red[w];
        atomicAdd(&g_accum, blk);
        __threadfence();
        int prev = atomicAdd(&g_done, 1);
        if (prev == PDIST_BLOCKS - 1) {
            g_done = 0;
            out[0] = -g_accum / (float)NPAIRS;
        }
    }
}

extern "C" void kernel_launch(void* const* d_in, const int* in_sizes, int n_in,
                              void* d_out, int out_size) {
    const float* matrix = (const float*)d_in[0];
    const int*   label  = (const int*)d_in[1];
    float* out = (float*)d_out;

    k_sort<<<SORT_CTAS, SORT_THREADS>>>(label);
    k_center<<<CENTER_CTAS, 256>>>(matrix);
    k_pdist<<<PDIST_BLOCKS, 256>>>(out);
}